// round 2
// baseline (speedup 1.0000x reference)
#include <cuda_runtime.h>
#include <math.h>

#define Bb   16
#define Ss   512
#define Hh   768
#define NHh  12
#define DHh  64
#define Ll   2
#define FFf  3072
#define Tt   (Bb*Ss)          // 8192 tokens
#define H3   (3*Hh)           // 2304

// ---------------- scratch (no allocations allowed) ----------------
__device__ float g_x[Tt*Hh];                    // hidden state      25 MB
__device__ float g_tmp[Tt*FFf];                 // qkv / wo / ff1   100 MB
__device__ float g_ctx[Tt*Hh];                  // attn ctx / ff2    25 MB
__device__ float g_scores[(size_t)Bb*NHh*Ss*Ss];// attn scores      201 MB
__device__ int   g_seg_first[Bb*Ss];
__device__ int   g_seg_cnt[Bb*Ss];
__device__ int   g_nseg[Bb];

// ---------------- helpers ----------------
__device__ __forceinline__ float block_reduce_sum_256(float v, float* red) {
    int t = threadIdx.x;
    red[t] = v; __syncthreads();
#pragma unroll
    for (int o = 128; o > 0; o >>= 1) {
        if (t < o) red[t] += red[t + o];
        __syncthreads();
    }
    float r = red[0];
    __syncthreads();
    return r;
}

// ---------------- embedding + LN ----------------
__global__ void embed_ln_kernel(const int* __restrict__ tok,
                                const float* __restrict__ emb,
                                const float* __restrict__ pos,
                                const float* __restrict__ g,
                                const float* __restrict__ bt) {
    int row = blockIdx.x;            // token index 0..8191
    int s   = row & (Ss - 1);
    int id  = tok[row * 2 + 1];
    __shared__ float y[Hh];
    __shared__ float red[256];
    int t = threadIdx.x;
    float part = 0.f;
    for (int j = t; j < Hh; j += 256) {
        float v = emb[(size_t)id * Hh + j] + pos[s * Hh + j];
        y[j] = v; part += v;
    }
    float mean = block_reduce_sum_256(part, red) * (1.f / Hh);
    part = 0.f;
    for (int j = t; j < Hh; j += 256) { float d = y[j] - mean; part += d * d; }
    float var = block_reduce_sum_256(part, red) * (1.f / Hh);
    float inv = rsqrtf(var + 1e-12f);
    for (int j = t; j < Hh; j += 256)
        g_x[(size_t)row * Hh + j] = (y[j] - mean) * inv * g[j] + bt[j];
}

// ---------------- residual add + LN ----------------
__global__ void add_ln_kernel(const float* __restrict__ x,
                              const float* __restrict__ tadd,
                              const float* __restrict__ g,
                              const float* __restrict__ bt,
                              float* __restrict__ out) {
    int row = blockIdx.x;
    size_t base = (size_t)row * Hh;
    __shared__ float y[Hh];
    __shared__ float red[256];
    int t = threadIdx.x;
    float part = 0.f;
    for (int j = t; j < Hh; j += 256) {
        float v = x[base + j] + tadd[base + j];
        y[j] = v; part += v;
    }
    float mean = block_reduce_sum_256(part, red) * (1.f / Hh);
    part = 0.f;
    for (int j = t; j < Hh; j += 256) { float d = y[j] - mean; part += d * d; }
    float var = block_reduce_sum_256(part, red) * (1.f / Hh);
    float inv = rsqrtf(var + 1e-12f);
    for (int j = t; j < Hh; j += 256)
        out[base + j] = (y[j] - mean) * inv * g[j] + bt[j];
}

// ---------------- tiled SGEMM: C = A[M,K] @ W[K,N] + bias, optional GELU ----------------
// BM=BN=128, BK=16, 256 threads, 8x8 per thread. M,N,K all multiples of tile dims here.
__global__ __launch_bounds__(256) void sgemm_kernel(const float* __restrict__ A,
                                                    const float* __restrict__ W,
                                                    const float* __restrict__ bias,
                                                    float* __restrict__ C,
                                                    int M, int N, int K, int act) {
    const int BM = 128, BN = 128, BK = 16;
    __shared__ float As[BK][BM + 4];
    __shared__ float Bs[BK][BN];
    int tid = threadIdx.x;
    int ty = tid >> 4, tx = tid & 15;
    int mBase = blockIdx.y * BM, nBase = blockIdx.x * BN;
    float acc[8][8] = {};
    for (int k0 = 0; k0 < K; k0 += BK) {
#pragma unroll
        for (int i = 0; i < 2; i++) {           // A tile: 128x16 = 512 float4
            int idx = tid + i * 256;
            int r = idx >> 2, c4 = (idx & 3) << 2;
            float4 v = *reinterpret_cast<const float4*>(&A[(size_t)(mBase + r) * K + k0 + c4]);
            As[c4 + 0][r] = v.x; As[c4 + 1][r] = v.y;
            As[c4 + 2][r] = v.z; As[c4 + 3][r] = v.w;
        }
#pragma unroll
        for (int i = 0; i < 2; i++) {           // B tile: 16x128 = 512 float4
            int idx = tid + i * 256;
            int r = idx >> 5, c4 = (idx & 31) << 2;
            *reinterpret_cast<float4*>(&Bs[r][c4]) =
                *reinterpret_cast<const float4*>(&W[(size_t)(k0 + r) * N + nBase + c4]);
        }
        __syncthreads();
#pragma unroll
        for (int kk = 0; kk < BK; kk++) {
            float a[8], bb[8];
#pragma unroll
            for (int i = 0; i < 8; i++) a[i] = As[kk][ty * 8 + i];
#pragma unroll
            for (int j = 0; j < 8; j++) bb[j] = Bs[kk][tx * 8 + j];
#pragma unroll
            for (int i = 0; i < 8; i++)
#pragma unroll
                for (int j = 0; j < 8; j++)
                    acc[i][j] = fmaf(a[i], bb[j], acc[i][j]);
        }
        __syncthreads();
    }
#pragma unroll
    for (int i = 0; i < 8; i++) {
        int m = mBase + ty * 8 + i;
#pragma unroll
        for (int j = 0; j < 8; j++) {
            int n = nBase + tx * 8 + j;
            float v = acc[i][j] + bias[n];
            if (act) v = 0.5f * v * (1.0f + erff(v * 0.70710678118654752f));
            C[(size_t)m * N + n] = v;
        }
    }
}

// ---------------- attention scores: S[b,h,q,k] = (Q . K) / 8 ----------------
__global__ __launch_bounds__(256) void attn_scores_kernel(const float* __restrict__ qkv) {
    __shared__ float Qs[64][65], Ks[64][65];
    int bh = blockIdx.z; int b = bh / NHh, h = bh - b * NHh;
    int qt = blockIdx.y * 64, kt = blockIdx.x * 64;
    int tid = threadIdx.x;
#pragma unroll
    for (int i = 0; i < 4; i++) {               // 64x64 = 1024 float4 each
        int idx = tid + i * 256;
        int r = idx >> 4, c4 = (idx & 15) << 2;
        float4 q4 = *reinterpret_cast<const float4*>(
            &qkv[(size_t)(b * Ss + qt + r) * H3 + h * DHh + c4]);
        Qs[r][c4] = q4.x; Qs[r][c4 + 1] = q4.y; Qs[r][c4 + 2] = q4.z; Qs[r][c4 + 3] = q4.w;
        float4 k4 = *reinterpret_cast<const float4*>(
            &qkv[(size_t)(b * Ss + kt + r) * H3 + Hh + h * DHh + c4]);
        Ks[r][c4] = k4.x; Ks[r][c4 + 1] = k4.y; Ks[r][c4 + 2] = k4.z; Ks[r][c4 + 3] = k4.w;
    }
    __syncthreads();
    int ty = tid >> 4, tx = tid & 15;
    float acc[4][4] = {};
#pragma unroll
    for (int d = 0; d < 64; d++) {
        float a[4], bv[4];
#pragma unroll
        for (int i = 0; i < 4; i++) a[i] = Qs[ty * 4 + i][d];
#pragma unroll
        for (int j = 0; j < 4; j++) bv[j] = Ks[tx * 4 + j][d];
#pragma unroll
        for (int i = 0; i < 4; i++)
#pragma unroll
            for (int j = 0; j < 4; j++)
                acc[i][j] = fmaf(a[i], bv[j], acc[i][j]);
    }
    size_t base = (size_t)bh * Ss * Ss;
#pragma unroll
    for (int i = 0; i < 4; i++)
#pragma unroll
        for (int j = 0; j < 4; j++)
            g_scores[base + (size_t)(qt + ty * 4 + i) * Ss + kt + tx * 4 + j] = acc[i][j] * 0.125f;
}

// ---------------- softmax over k (rows of 512) ----------------
__global__ void softmax_kernel() {
    int q = blockIdx.x, bh = blockIdx.y;
    float* row = &g_scores[((size_t)bh * Ss + q) * Ss];
    int t = threadIdx.x;
    __shared__ float red[256];
    float v0 = row[t], v1 = row[t + 256];
    red[t] = fmaxf(v0, v1); __syncthreads();
#pragma unroll
    for (int o = 128; o > 0; o >>= 1) {
        if (t < o) red[t] = fmaxf(red[t], red[t + o]);
        __syncthreads();
    }
    float m = red[0]; __syncthreads();
    float e0 = __expf(v0 - m), e1 = __expf(v1 - m);
    float s = block_reduce_sum_256(e0 + e1, red);
    float inv = 1.0f / s;
    row[t] = e0 * inv; row[t + 256] = e1 * inv;
}

// ---------------- attn output: ctx = P @ V ----------------
__global__ __launch_bounds__(256) void attn_av_kernel(const float* __restrict__ qkv) {
    __shared__ float Ps[64][65], Vs[64][65];
    int bh = blockIdx.y; int b = bh / NHh, h = bh - b * NHh;
    int qt = blockIdx.x * 64;
    int tid = threadIdx.x, ty = tid >> 4, tx = tid & 15;
    float acc[4][4] = {};
    size_t sbase = (size_t)bh * Ss * Ss;
    for (int kt = 0; kt < Ss; kt += 64) {
#pragma unroll
        for (int i = 0; i < 4; i++) {
            int idx = tid + i * 256;
            int r = idx >> 4, c4 = (idx & 15) << 2;
            float4 p4 = *reinterpret_cast<const float4*>(
                &g_scores[sbase + (size_t)(qt + r) * Ss + kt + c4]);
            Ps[r][c4] = p4.x; Ps[r][c4 + 1] = p4.y; Ps[r][c4 + 2] = p4.z; Ps[r][c4 + 3] = p4.w;
            float4 v4 = *reinterpret_cast<const float4*>(
                &qkv[(size_t)(b * Ss + kt + r) * H3 + 2 * Hh + h * DHh + c4]);
            Vs[r][c4] = v4.x; Vs[r][c4 + 1] = v4.y; Vs[r][c4 + 2] = v4.z; Vs[r][c4 + 3] = v4.w;
        }
        __syncthreads();
#pragma unroll
        for (int kk = 0; kk < 64; kk++) {
            float a[4], bv[4];
#pragma unroll
            for (int i = 0; i < 4; i++) a[i] = Ps[ty * 4 + i][kk];
#pragma unroll
            for (int j = 0; j < 4; j++) bv[j] = Vs[kk][tx * 4 + j];
#pragma unroll
            for (int i = 0; i < 4; i++)
#pragma unroll
                for (int j = 0; j < 4; j++)
                    acc[i][j] = fmaf(a[i], bv[j], acc[i][j]);
        }
        __syncthreads();
    }
#pragma unroll
    for (int i = 0; i < 4; i++)
#pragma unroll
        for (int j = 0; j < 4; j++)
            g_ctx[(size_t)(b * Ss + qt + ty * 4 + i) * Hh + h * DHh + tx * 4 + j] = acc[i][j];
}

// ---------------- segment bookkeeping (deterministic) ----------------
__global__ void seg_prep_kernel(const int* __restrict__ tok) {
    int b = blockIdx.x, s = threadIdx.x;
    __shared__ int sc[Ss];
    __shared__ int cnt[Ss];
    int wid = tok[(b * Ss + s) * 2];
    int isnew = (s == 0) ? 1 : (wid != tok[(b * Ss + s - 1) * 2] ? 1 : 0);
    sc[s] = isnew; cnt[s] = 0; __syncthreads();
    for (int off = 1; off < Ss; off <<= 1) {
        int v = (s >= off) ? sc[s - off] : 0;
        __syncthreads();
        sc[s] += v;
        __syncthreads();
    }
    int gid = sc[s] - 1;
    if (tok[(b * Ss + s) * 2 + 1] != 0) atomicAdd(&cnt[gid], 1);
    if (isnew) g_seg_first[b * Ss + gid] = s;
    __syncthreads();
    g_seg_cnt[b * Ss + s] = cnt[s];
    if (s == Ss - 1) g_nseg[b] = gid + 1;
}

__global__ void seg_mean_kernel(const int* __restrict__ tok, float* __restrict__ out) {
    int g = blockIdx.x, b = blockIdx.y;
    int n = g_nseg[b];
    if (g >= n) return;                         // out already zeroed
    int c = g_seg_cnt[b * Ss + g];
    if (c == 0) return;
    int start = g_seg_first[b * Ss + g];
    int end = (g + 1 < n) ? g_seg_first[b * Ss + g + 1] : Ss;
    __shared__ unsigned char mf[Ss];
    for (int s = threadIdx.x; s < Ss; s += 128)
        mf[s] = (tok[(b * Ss + s) * 2 + 1] != 0);
    __syncthreads();
    float inv = 1.0f / (float)c;
    for (int j = threadIdx.x; j < Hh; j += 128) {
        float sum = 0.f;
        for (int s = start; s < end; s++)
            if (mf[s]) sum += g_x[(size_t)(b * Ss + s) * Hh + j];
        out[(size_t)(b * Ss + g) * Hh + j] = sum * inv;
    }
}

// ---------------- launch ----------------
extern "C" void kernel_launch(void* const* d_in, const int* in_sizes, int n_in,
                              void* d_out, int out_size) {
    const int*   tok  = (const int*)  d_in[0];
    const float* emb  = (const float*)d_in[1];
    const float* pos  = (const float*)d_in[2];
    const float* lng  = (const float*)d_in[3];
    const float* lnb  = (const float*)d_in[4];
    const float* Wqkv = (const float*)d_in[5];
    const float* bqkv = (const float*)d_in[6];
    const float* Wo   = (const float*)d_in[7];
    const float* bo   = (const float*)d_in[8];
    const float* ln1g = (const float*)d_in[9];
    const float* ln1b = (const float*)d_in[10];
    const float* Wff1 = (const float*)d_in[11];
    const float* bff1 = (const float*)d_in[12];
    const float* Wff2 = (const float*)d_in[13];
    const float* bff2 = (const float*)d_in[14];
    const float* ln2g = (const float*)d_in[15];
    const float* ln2b = (const float*)d_in[16];
    float* out = (float*)d_out;

    void* p;
    cudaGetSymbolAddress(&p, g_x);   float* x   = (float*)p;
    cudaGetSymbolAddress(&p, g_tmp); float* tmp = (float*)p;
    cudaGetSymbolAddress(&p, g_ctx); float* ctx = (float*)p;

    cudaMemsetAsync(d_out, 0, (size_t)out_size * sizeof(float), 0);

    embed_ln_kernel<<<Tt, 256>>>(tok, emb, pos, lng, lnb);

    for (int l = 0; l < Ll; l++) {
        // QKV projection: [8192,768] @ [768,2304]
        sgemm_kernel<<<dim3(H3 / 128, Tt / 128), 256>>>(
            x, Wqkv + (size_t)l * Hh * H3, bqkv + l * H3, tmp, Tt, H3, Hh, 0);
        // attention
        attn_scores_kernel<<<dim3(8, 8, Bb * NHh), 256>>>(tmp);
        softmax_kernel<<<dim3(Ss, Bb * NHh), 256>>>();
        attn_av_kernel<<<dim3(8, Bb * NHh), 256>>>(tmp);
        // output projection: [8192,768] @ [768,768] (tmp reused — qkv dead)
        sgemm_kernel<<<dim3(Hh / 128, Tt / 128), 256>>>(
            ctx, Wo + (size_t)l * Hh * Hh, bo + l * Hh, tmp, Tt, Hh, Hh, 0);
        add_ln_kernel<<<Tt, 256>>>(x, tmp, ln1g + l * Hh, ln1b + l * Hh, x);
        // FFN
        sgemm_kernel<<<dim3(FFf / 128, Tt / 128), 256>>>(
            x, Wff1 + (size_t)l * Hh * FFf, bff1 + l * FFf, tmp, Tt, FFf, Hh, 1);
        sgemm_kernel<<<dim3(Hh / 128, Tt / 128), 256>>>(
            tmp, Wff2 + (size_t)l * FFf * Hh, bff2 + l * Hh, ctx, Tt, Hh, FFf, 0);
        add_ln_kernel<<<Tt, 256>>>(x, ctx, ln2g + l * Hh, ln2b + l * Hh, x);
    }

    seg_prep_kernel<<<Bb, Ss>>>(tok);
    seg_mean_kernel<<<dim3(Ss, Bb), 128>>>(tok, out);
}

// round 3
// speedup vs baseline: 2.1706x; 2.1706x over previous
#include <cuda_runtime.h>
#include <math.h>
#include <stdint.h>

#define Bb   16
#define Ss   512
#define Hh   768
#define NHh  12
#define DHh  64
#define Ll   2
#define FFf  3072
#define Tt   (Bb*Ss)          // 8192 tokens
#define H3   (3*Hh)           // 2304

// ---------------- scratch (no allocations allowed) ----------------
__device__ float g_x[Tt*Hh];                    // hidden state      25 MB
__device__ float g_tmp[Tt*FFf];                 // qkv / wo / ff1   100 MB
__device__ float g_ctx[Tt*Hh];                  // attn ctx / ff2    25 MB
__device__ float g_scores[(size_t)Bb*NHh*Ss*Ss];// attn scores      201 MB
__device__ int   g_seg_first[Bb*Ss];
__device__ int   g_seg_cnt[Bb*Ss];
__device__ int   g_nseg[Bb];

// ---------------- helpers ----------------
__device__ __forceinline__ float block_reduce_sum_256(float v, float* red) {
    int t = threadIdx.x;
    red[t] = v; __syncthreads();
#pragma unroll
    for (int o = 128; o > 0; o >>= 1) {
        if (t < o) red[t] += red[t + o];
        __syncthreads();
    }
    float r = red[0];
    __syncthreads();
    return r;
}

__device__ __forceinline__ uint32_t f2tf32(float x) {
    uint32_t r;
    asm("cvt.rna.tf32.f32 %0, %1;" : "=r"(r) : "f"(x));
    return r;
}

__device__ __forceinline__ void mma_tf32(float* c, const uint32_t* a, const uint32_t* b) {
    asm volatile(
        "mma.sync.aligned.m16n8k8.row.col.f32.tf32.tf32.f32 "
        "{%0,%1,%2,%3}, {%4,%5,%6,%7}, {%8,%9}, {%0,%1,%2,%3};"
        : "+f"(c[0]), "+f"(c[1]), "+f"(c[2]), "+f"(c[3])
        : "r"(a[0]), "r"(a[1]), "r"(a[2]), "r"(a[3]), "r"(b[0]), "r"(b[1]));
}

// ---------------- embedding + LN ----------------
__global__ void embed_ln_kernel(const int* __restrict__ tok,
                                const float* __restrict__ emb,
                                const float* __restrict__ pos,
                                const float* __restrict__ g,
                                const float* __restrict__ bt) {
    int row = blockIdx.x;            // token index 0..8191
    int s   = row & (Ss - 1);
    int id  = tok[row * 2 + 1];
    __shared__ float y[Hh];
    __shared__ float red[256];
    int t = threadIdx.x;
    float part = 0.f;
    for (int j = t; j < Hh; j += 256) {
        float v = emb[(size_t)id * Hh + j] + pos[s * Hh + j];
        y[j] = v; part += v;
    }
    float mean = block_reduce_sum_256(part, red) * (1.f / Hh);
    part = 0.f;
    for (int j = t; j < Hh; j += 256) { float d = y[j] - mean; part += d * d; }
    float var = block_reduce_sum_256(part, red) * (1.f / Hh);
    float inv = rsqrtf(var + 1e-12f);
    for (int j = t; j < Hh; j += 256)
        g_x[(size_t)row * Hh + j] = (y[j] - mean) * inv * g[j] + bt[j];
}

// ---------------- residual add + LN ----------------
__global__ void add_ln_kernel(const float* __restrict__ x,
                              const float* __restrict__ tadd,
                              const float* __restrict__ g,
                              const float* __restrict__ bt,
                              float* __restrict__ out) {
    int row = blockIdx.x;
    size_t base = (size_t)row * Hh;
    __shared__ float y[Hh];
    __shared__ float red[256];
    int t = threadIdx.x;
    float part = 0.f;
    for (int j = t; j < Hh; j += 256) {
        float v = x[base + j] + tadd[base + j];
        y[j] = v; part += v;
    }
    float mean = block_reduce_sum_256(part, red) * (1.f / Hh);
    part = 0.f;
    for (int j = t; j < Hh; j += 256) { float d = y[j] - mean; part += d * d; }
    float var = block_reduce_sum_256(part, red) * (1.f / Hh);
    float inv = rsqrtf(var + 1e-12f);
    for (int j = t; j < Hh; j += 256)
        out[base + j] = (y[j] - mean) * inv * g[j] + bt[j];
}

// ---------------- TF32 tensor-core GEMM: C = A[M,K] @ W[K,N] + bias, opt GELU ----
// BM=BN=128, BK=32. 256 threads = 8 warps (2x4), warp tile 64x32 via m16n8k8.
// As: [m][k] stride 36 (frag reads hit all 32 banks: 4*g+tig)
// Bs: [k][n] stride 132 (frag reads hit all 32 banks: 4*tig+g)
#define AS_STRIDE 36
#define BS_STRIDE 132
__global__ __launch_bounds__(256) void gemm_tf32_kernel(const float* __restrict__ A,
                                                        const float* __restrict__ W,
                                                        const float* __restrict__ bias,
                                                        float* __restrict__ C,
                                                        int M, int N, int K, int act) {
    __shared__ uint32_t As[128 * AS_STRIDE];
    __shared__ uint32_t Bs[32 * BS_STRIDE];
    int tid  = threadIdx.x;
    int lane = tid & 31;
    int warp = tid >> 5;
    int g    = lane >> 2, tig = lane & 3;
    int wm   = warp >> 2, wn = warp & 3;           // 2 x 4 warp grid
    int mBase = blockIdx.y * 128, nBase = blockIdx.x * 128;

    float acc[4][4][4];
#pragma unroll
    for (int i = 0; i < 4; i++)
#pragma unroll
        for (int j = 0; j < 4; j++)
#pragma unroll
            for (int r = 0; r < 4; r++) acc[i][j][r] = 0.f;

    for (int k0 = 0; k0 < K; k0 += 32) {
        // A tile 128x32: 1024 float4, 4 per thread
#pragma unroll
        for (int i = 0; i < 4; i++) {
            int idx = tid + i * 256;
            int r = idx >> 3, c4 = (idx & 7) << 2;
            float4 v = *reinterpret_cast<const float4*>(&A[(size_t)(mBase + r) * K + k0 + c4]);
            uint32_t* p = &As[r * AS_STRIDE + c4];
            p[0] = f2tf32(v.x); p[1] = f2tf32(v.y);
            p[2] = f2tf32(v.z); p[3] = f2tf32(v.w);
        }
        // B tile 32x128
#pragma unroll
        for (int i = 0; i < 4; i++) {
            int idx = tid + i * 256;
            int r = idx >> 5, c4 = (idx & 31) << 2;
            float4 v = *reinterpret_cast<const float4*>(&W[(size_t)(k0 + r) * N + nBase + c4]);
            uint32_t* p = &Bs[r * BS_STRIDE + c4];
            p[0] = f2tf32(v.x); p[1] = f2tf32(v.y);
            p[2] = f2tf32(v.z); p[3] = f2tf32(v.w);
        }
        __syncthreads();
#pragma unroll
        for (int kk = 0; kk < 32; kk += 8) {
            uint32_t a[4][4], b[4][2];
#pragma unroll
            for (int mi = 0; mi < 4; mi++) {
                int rm = wm * 64 + mi * 16 + g;
                a[mi][0] = As[rm * AS_STRIDE + kk + tig];
                a[mi][1] = As[(rm + 8) * AS_STRIDE + kk + tig];
                a[mi][2] = As[rm * AS_STRIDE + kk + tig + 4];
                a[mi][3] = As[(rm + 8) * AS_STRIDE + kk + tig + 4];
            }
#pragma unroll
            for (int ni = 0; ni < 4; ni++) {
                int cn = wn * 32 + ni * 8 + g;
                b[ni][0] = Bs[(kk + tig) * BS_STRIDE + cn];
                b[ni][1] = Bs[(kk + tig + 4) * BS_STRIDE + cn];
            }
#pragma unroll
            for (int mi = 0; mi < 4; mi++)
#pragma unroll
                for (int ni = 0; ni < 4; ni++)
                    mma_tf32(acc[mi][ni], a[mi], b[ni]);
        }
        __syncthreads();
    }
    // epilogue: bias + optional exact GELU, float2 stores
#pragma unroll
    for (int mi = 0; mi < 4; mi++) {
        int rm0 = mBase + wm * 64 + mi * 16 + g;
#pragma unroll
        for (int ni = 0; ni < 4; ni++) {
            int cn = nBase + wn * 32 + ni * 8 + 2 * tig;
            float b0 = bias[cn], b1 = bias[cn + 1];
            float v0 = acc[mi][ni][0] + b0;
            float v1 = acc[mi][ni][1] + b1;
            float v2 = acc[mi][ni][2] + b0;
            float v3 = acc[mi][ni][3] + b1;
            if (act) {
                v0 = 0.5f * v0 * (1.0f + erff(v0 * 0.70710678118654752f));
                v1 = 0.5f * v1 * (1.0f + erff(v1 * 0.70710678118654752f));
                v2 = 0.5f * v2 * (1.0f + erff(v2 * 0.70710678118654752f));
                v3 = 0.5f * v3 * (1.0f + erff(v3 * 0.70710678118654752f));
            }
            *reinterpret_cast<float2*>(&C[(size_t)rm0 * N + cn])       = make_float2(v0, v1);
            *reinterpret_cast<float2*>(&C[(size_t)(rm0 + 8) * N + cn]) = make_float2(v2, v3);
        }
    }
}

// ---------------- attention scores: S[b,h,q,k] = (Q . K) / 8 ----------------
__global__ __launch_bounds__(256) void attn_scores_kernel(const float* __restrict__ qkv) {
    __shared__ float Qs[64][65], Ks[64][65];
    int bh = blockIdx.z; int b = bh / NHh, h = bh - b * NHh;
    int qt = blockIdx.y * 64, kt = blockIdx.x * 64;
    int tid = threadIdx.x;
#pragma unroll
    for (int i = 0; i < 4; i++) {               // 64x64 = 1024 float4 each
        int idx = tid + i * 256;
        int r = idx >> 4, c4 = (idx & 15) << 2;
        float4 q4 = *reinterpret_cast<const float4*>(
            &qkv[(size_t)(b * Ss + qt + r) * H3 + h * DHh + c4]);
        Qs[r][c4] = q4.x; Qs[r][c4 + 1] = q4.y; Qs[r][c4 + 2] = q4.z; Qs[r][c4 + 3] = q4.w;
        float4 k4 = *reinterpret_cast<const float4*>(
            &qkv[(size_t)(b * Ss + kt + r) * H3 + Hh + h * DHh + c4]);
        Ks[r][c4] = k4.x; Ks[r][c4 + 1] = k4.y; Ks[r][c4 + 2] = k4.z; Ks[r][c4 + 3] = k4.w;
    }
    __syncthreads();
    int ty = tid >> 4, tx = tid & 15;
    float acc[4][4] = {};
#pragma unroll
    for (int d = 0; d < 64; d++) {
        float a[4], bv[4];
#pragma unroll
        for (int i = 0; i < 4; i++) a[i] = Qs[ty * 4 + i][d];
#pragma unroll
        for (int j = 0; j < 4; j++) bv[j] = Ks[tx * 4 + j][d];
#pragma unroll
        for (int i = 0; i < 4; i++)
#pragma unroll
            for (int j = 0; j < 4; j++)
                acc[i][j] = fmaf(a[i], bv[j], acc[i][j]);
    }
    size_t base = (size_t)bh * Ss * Ss;
#pragma unroll
    for (int i = 0; i < 4; i++)
#pragma unroll
        for (int j = 0; j < 4; j++)
            g_scores[base + (size_t)(qt + ty * 4 + i) * Ss + kt + tx * 4 + j] = acc[i][j] * 0.125f;
}

// ---------------- softmax over k (rows of 512) ----------------
__global__ void softmax_kernel() {
    int q = blockIdx.x, bh = blockIdx.y;
    float* row = &g_scores[((size_t)bh * Ss + q) * Ss];
    int t = threadIdx.x;
    __shared__ float red[256];
    float v0 = row[t], v1 = row[t + 256];
    red[t] = fmaxf(v0, v1); __syncthreads();
#pragma unroll
    for (int o = 128; o > 0; o >>= 1) {
        if (t < o) red[t] = fmaxf(red[t], red[t + o]);
        __syncthreads();
    }
    float m = red[0]; __syncthreads();
    float e0 = __expf(v0 - m), e1 = __expf(v1 - m);
    float s = block_reduce_sum_256(e0 + e1, red);
    float inv = 1.0f / s;
    row[t] = e0 * inv; row[t + 256] = e1 * inv;
}

// ---------------- attn output: ctx = P @ V ----------------
__global__ __launch_bounds__(256) void attn_av_kernel(const float* __restrict__ qkv) {
    __shared__ float Ps[64][65], Vs[64][65];
    int bh = blockIdx.y; int b = bh / NHh, h = bh - b * NHh;
    int qt = blockIdx.x * 64;
    int tid = threadIdx.x, ty = tid >> 4, tx = tid & 15;
    float acc[4][4] = {};
    size_t sbase = (size_t)bh * Ss * Ss;
    for (int kt = 0; kt < Ss; kt += 64) {
#pragma unroll
        for (int i = 0; i < 4; i++) {
            int idx = tid + i * 256;
            int r = idx >> 4, c4 = (idx & 15) << 2;
            float4 p4 = *reinterpret_cast<const float4*>(
                &g_scores[sbase + (size_t)(qt + r) * Ss + kt + c4]);
            Ps[r][c4] = p4.x; Ps[r][c4 + 1] = p4.y; Ps[r][c4 + 2] = p4.z; Ps[r][c4 + 3] = p4.w;
            float4 v4 = *reinterpret_cast<const float4*>(
                &qkv[(size_t)(b * Ss + kt + r) * H3 + 2 * Hh + h * DHh + c4]);
            Vs[r][c4] = v4.x; Vs[r][c4 + 1] = v4.y; Vs[r][c4 + 2] = v4.z; Vs[r][c4 + 3] = v4.w;
        }
        __syncthreads();
#pragma unroll
        for (int kk = 0; kk < 64; kk++) {
            float a[4], bv[4];
#pragma unroll
            for (int i = 0; i < 4; i++) a[i] = Ps[ty * 4 + i][kk];
#pragma unroll
            for (int j = 0; j < 4; j++) bv[j] = Vs[kk][tx * 4 + j];
#pragma unroll
            for (int i = 0; i < 4; i++)
#pragma unroll
                for (int j = 0; j < 4; j++)
                    acc[i][j] = fmaf(a[i], bv[j], acc[i][j]);
        }
        __syncthreads();
    }
#pragma unroll
    for (int i = 0; i < 4; i++)
#pragma unroll
        for (int j = 0; j < 4; j++)
            g_ctx[(size_t)(b * Ss + qt + ty * 4 + i) * Hh + h * DHh + tx * 4 + j] = acc[i][j];
}

// ---------------- segment bookkeeping (deterministic) ----------------
__global__ void seg_prep_kernel(const int* __restrict__ tok) {
    int b = blockIdx.x, s = threadIdx.x;
    __shared__ int sc[Ss];
    __shared__ int cnt[Ss];
    int wid = tok[(b * Ss + s) * 2];
    int isnew = (s == 0) ? 1 : (wid != tok[(b * Ss + s - 1) * 2] ? 1 : 0);
    sc[s] = isnew; cnt[s] = 0; __syncthreads();
    for (int off = 1; off < Ss; off <<= 1) {
        int v = (s >= off) ? sc[s - off] : 0;
        __syncthreads();
        sc[s] += v;
        __syncthreads();
    }
    int gid = sc[s] - 1;
    if (tok[(b * Ss + s) * 2 + 1] != 0) atomicAdd(&cnt[gid], 1);
    if (isnew) g_seg_first[b * Ss + gid] = s;
    __syncthreads();
    g_seg_cnt[b * Ss + s] = cnt[s];
    if (s == Ss - 1) g_nseg[b] = gid + 1;
}

__global__ void seg_mean_kernel(const int* __restrict__ tok, float* __restrict__ out) {
    int g = blockIdx.x, b = blockIdx.y;
    int n = g_nseg[b];
    if (g >= n) return;                         // out already zeroed
    int c = g_seg_cnt[b * Ss + g];
    if (c == 0) return;
    int start = g_seg_first[b * Ss + g];
    int end = (g + 1 < n) ? g_seg_first[b * Ss + g + 1] : Ss;
    __shared__ unsigned char mf[Ss];
    for (int s = threadIdx.x; s < Ss; s += 128)
        mf[s] = (tok[(b * Ss + s) * 2 + 1] != 0);
    __syncthreads();
    float inv = 1.0f / (float)c;
    for (int j = threadIdx.x; j < Hh; j += 128) {
        float sum = 0.f;
        for (int s = start; s < end; s++)
            if (mf[s]) sum += g_x[(size_t)(b * Ss + s) * Hh + j];
        out[(size_t)(b * Ss + g) * Hh + j] = sum * inv;
    }
}

// ---------------- launch ----------------
extern "C" void kernel_launch(void* const* d_in, const int* in_sizes, int n_in,
                              void* d_out, int out_size) {
    const int*   tok  = (const int*)  d_in[0];
    const float* emb  = (const float*)d_in[1];
    const float* pos  = (const float*)d_in[2];
    const float* lng  = (const float*)d_in[3];
    const float* lnb  = (const float*)d_in[4];
    const float* Wqkv = (const float*)d_in[5];
    const float* bqkv = (const float*)d_in[6];
    const float* Wo   = (const float*)d_in[7];
    const float* bo   = (const float*)d_in[8];
    const float* ln1g = (const float*)d_in[9];
    const float* ln1b = (const float*)d_in[10];
    const float* Wff1 = (const float*)d_in[11];
    const float* bff1 = (const float*)d_in[12];
    const float* Wff2 = (const float*)d_in[13];
    const float* bff2 = (const float*)d_in[14];
    const float* ln2g = (const float*)d_in[15];
    const float* ln2b = (const float*)d_in[16];
    float* out = (float*)d_out;

    void* p;
    cudaGetSymbolAddress(&p, g_x);   float* x   = (float*)p;
    cudaGetSymbolAddress(&p, g_tmp); float* tmp = (float*)p;
    cudaGetSymbolAddress(&p, g_ctx); float* ctx = (float*)p;

    cudaMemsetAsync(d_out, 0, (size_t)out_size * sizeof(float), 0);

    embed_ln_kernel<<<Tt, 256>>>(tok, emb, pos, lng, lnb);

    for (int l = 0; l < Ll; l++) {
        // QKV projection: [8192,768] @ [768,2304]
        gemm_tf32_kernel<<<dim3(H3 / 128, Tt / 128), 256>>>(
            x, Wqkv + (size_t)l * Hh * H3, bqkv + l * H3, tmp, Tt, H3, Hh, 0);
        // attention
        attn_scores_kernel<<<dim3(8, 8, Bb * NHh), 256>>>(tmp);
        softmax_kernel<<<dim3(Ss, Bb * NHh), 256>>>();
        attn_av_kernel<<<dim3(8, Bb * NHh), 256>>>(tmp);
        // output projection: [8192,768] @ [768,768] (tmp reused — qkv dead)
        gemm_tf32_kernel<<<dim3(Hh / 128, Tt / 128), 256>>>(
            ctx, Wo + (size_t)l * Hh * Hh, bo + l * Hh, tmp, Tt, Hh, Hh, 0);
        add_ln_kernel<<<Tt, 256>>>(x, tmp, ln1g + l * Hh, ln1b + l * Hh, x);
        // FFN
        gemm_tf32_kernel<<<dim3(FFf / 128, Tt / 128), 256>>>(
            x, Wff1 + (size_t)l * Hh * FFf, bff1 + l * FFf, tmp, Tt, FFf, Hh, 1);
        gemm_tf32_kernel<<<dim3(Hh / 128, Tt / 128), 256>>>(
            tmp, Wff2 + (size_t)l * FFf * Hh, bff2 + l * Hh, ctx, Tt, Hh, FFf, 0);
        add_ln_kernel<<<Tt, 256>>>(x, ctx, ln2g + l * Hh, ln2b + l * Hh, x);
    }

    seg_prep_kernel<<<Bb, Ss>>>(tok);
    seg_mean_kernel<<<dim3(Ss, Bb), 128>>>(tok, out);
}

// round 4
// speedup vs baseline: 2.8620x; 1.3185x over previous
#include <cuda_runtime.h>
#include <math.h>
#include <stdint.h>

#define Bb   16
#define Ss   512
#define Hh   768
#define NHh  12
#define DHh  64
#define Ll   2
#define FFf  3072
#define Tt   (Bb*Ss)          // 8192 tokens
#define H3   (3*Hh)           // 2304

// ---------------- scratch (no allocations allowed) ----------------
__device__ float g_x[Tt*Hh];                    // hidden state      25 MB
__device__ float g_tmp[Tt*FFf];                 // qkv / wo / ff1   100 MB
__device__ float g_ctx[Tt*Hh];                  // attn ctx / ff2    25 MB
__device__ int   g_seg_first[Bb*Ss];
__device__ int   g_seg_cnt[Bb*Ss];
__device__ int   g_nseg[Bb];

// ---------------- helpers ----------------
__device__ __forceinline__ float block_reduce_sum_256(float v, float* red) {
    int t = threadIdx.x;
    red[t] = v; __syncthreads();
#pragma unroll
    for (int o = 128; o > 0; o >>= 1) {
        if (t < o) red[t] += red[t + o];
        __syncthreads();
    }
    float r = red[0];
    __syncthreads();
    return r;
}

__device__ __forceinline__ uint32_t f2tf32(float x) {
    uint32_t r;
    asm("cvt.rna.tf32.f32 %0, %1;" : "=r"(r) : "f"(x));
    return r;
}

__device__ __forceinline__ void mma_tf32(float* c, const uint32_t* a, const uint32_t* b) {
    asm volatile(
        "mma.sync.aligned.m16n8k8.row.col.f32.tf32.tf32.f32 "
        "{%0,%1,%2,%3}, {%4,%5,%6,%7}, {%8,%9}, {%0,%1,%2,%3};"
        : "+f"(c[0]), "+f"(c[1]), "+f"(c[2]), "+f"(c[3])
        : "r"(a[0]), "r"(a[1]), "r"(a[2]), "r"(a[3]), "r"(b[0]), "r"(b[1]));
}

// ---------------- embedding + LN ----------------
__global__ void embed_ln_kernel(const int* __restrict__ tok,
                                const float* __restrict__ emb,
                                const float* __restrict__ pos,
                                const float* __restrict__ g,
                                const float* __restrict__ bt) {
    int row = blockIdx.x;
    int s   = row & (Ss - 1);
    int id  = tok[row * 2 + 1];
    __shared__ float y[Hh];
    __shared__ float red[256];
    int t = threadIdx.x;
    float part = 0.f;
    for (int j = t; j < Hh; j += 256) {
        float v = emb[(size_t)id * Hh + j] + pos[s * Hh + j];
        y[j] = v; part += v;
    }
    float mean = block_reduce_sum_256(part, red) * (1.f / Hh);
    part = 0.f;
    for (int j = t; j < Hh; j += 256) { float d = y[j] - mean; part += d * d; }
    float var = block_reduce_sum_256(part, red) * (1.f / Hh);
    float inv = rsqrtf(var + 1e-12f);
    for (int j = t; j < Hh; j += 256)
        g_x[(size_t)row * Hh + j] = (y[j] - mean) * inv * g[j] + bt[j];
}

// ---------------- residual add + LN ----------------
__global__ void add_ln_kernel(const float* __restrict__ x,
                              const float* __restrict__ tadd,
                              const float* __restrict__ g,
                              const float* __restrict__ bt,
                              float* __restrict__ out) {
    int row = blockIdx.x;
    size_t base = (size_t)row * Hh;
    __shared__ float y[Hh];
    __shared__ float red[256];
    int t = threadIdx.x;
    float part = 0.f;
    for (int j = t; j < Hh; j += 256) {
        float v = x[base + j] + tadd[base + j];
        y[j] = v; part += v;
    }
    float mean = block_reduce_sum_256(part, red) * (1.f / Hh);
    part = 0.f;
    for (int j = t; j < Hh; j += 256) { float d = y[j] - mean; part += d * d; }
    float var = block_reduce_sum_256(part, red) * (1.f / Hh);
    float inv = rsqrtf(var + 1e-12f);
    for (int j = t; j < Hh; j += 256)
        out[base + j] = (y[j] - mean) * inv * g[j] + bt[j];
}

// ---------------- TF32 tensor-core GEMM: C = A[M,K] @ W[K,N] + bias, opt GELU ----
#define AS_STRIDE 36
#define BS_STRIDE 132
__global__ __launch_bounds__(256) void gemm_tf32_kernel(const float* __restrict__ A,
                                                        const float* __restrict__ W,
                                                        const float* __restrict__ bias,
                                                        float* __restrict__ C,
                                                        int M, int N, int K, int act) {
    __shared__ uint32_t As[128 * AS_STRIDE];
    __shared__ uint32_t Bs[32 * BS_STRIDE];
    int tid  = threadIdx.x;
    int lane = tid & 31;
    int warp = tid >> 5;
    int g    = lane >> 2, tig = lane & 3;
    int wm   = warp >> 2, wn = warp & 3;
    int mBase = blockIdx.y * 128, nBase = blockIdx.x * 128;

    float acc[4][4][4];
#pragma unroll
    for (int i = 0; i < 4; i++)
#pragma unroll
        for (int j = 0; j < 4; j++)
#pragma unroll
            for (int r = 0; r < 4; r++) acc[i][j][r] = 0.f;

    for (int k0 = 0; k0 < K; k0 += 32) {
#pragma unroll
        for (int i = 0; i < 4; i++) {
            int idx = tid + i * 256;
            int r = idx >> 3, c4 = (idx & 7) << 2;
            float4 v = *reinterpret_cast<const float4*>(&A[(size_t)(mBase + r) * K + k0 + c4]);
            uint32_t* p = &As[r * AS_STRIDE + c4];
            p[0] = f2tf32(v.x); p[1] = f2tf32(v.y);
            p[2] = f2tf32(v.z); p[3] = f2tf32(v.w);
        }
#pragma unroll
        for (int i = 0; i < 4; i++) {
            int idx = tid + i * 256;
            int r = idx >> 5, c4 = (idx & 31) << 2;
            float4 v = *reinterpret_cast<const float4*>(&W[(size_t)(k0 + r) * N + nBase + c4]);
            uint32_t* p = &Bs[r * BS_STRIDE + c4];
            p[0] = f2tf32(v.x); p[1] = f2tf32(v.y);
            p[2] = f2tf32(v.z); p[3] = f2tf32(v.w);
        }
        __syncthreads();
#pragma unroll
        for (int kk = 0; kk < 32; kk += 8) {
            uint32_t a[4][4], b[4][2];
#pragma unroll
            for (int mi = 0; mi < 4; mi++) {
                int rm = wm * 64 + mi * 16 + g;
                a[mi][0] = As[rm * AS_STRIDE + kk + tig];
                a[mi][1] = As[(rm + 8) * AS_STRIDE + kk + tig];
                a[mi][2] = As[rm * AS_STRIDE + kk + tig + 4];
                a[mi][3] = As[(rm + 8) * AS_STRIDE + kk + tig + 4];
            }
#pragma unroll
            for (int ni = 0; ni < 4; ni++) {
                int cn = wn * 32 + ni * 8 + g;
                b[ni][0] = Bs[(kk + tig) * BS_STRIDE + cn];
                b[ni][1] = Bs[(kk + tig + 4) * BS_STRIDE + cn];
            }
#pragma unroll
            for (int mi = 0; mi < 4; mi++)
#pragma unroll
                for (int ni = 0; ni < 4; ni++)
                    mma_tf32(acc[mi][ni], a[mi], b[ni]);
        }
        __syncthreads();
    }
#pragma unroll
    for (int mi = 0; mi < 4; mi++) {
        int rm0 = mBase + wm * 64 + mi * 16 + g;
#pragma unroll
        for (int ni = 0; ni < 4; ni++) {
            int cn = nBase + wn * 32 + ni * 8 + 2 * tig;
            float b0 = bias[cn], b1 = bias[cn + 1];
            float v0 = acc[mi][ni][0] + b0;
            float v1 = acc[mi][ni][1] + b1;
            float v2 = acc[mi][ni][2] + b0;
            float v3 = acc[mi][ni][3] + b1;
            if (act) {
                v0 = 0.5f * v0 * (1.0f + erff(v0 * 0.70710678118654752f));
                v1 = 0.5f * v1 * (1.0f + erff(v1 * 0.70710678118654752f));
                v2 = 0.5f * v2 * (1.0f + erff(v2 * 0.70710678118654752f));
                v3 = 0.5f * v3 * (1.0f + erff(v3 * 0.70710678118654752f));
            }
            *reinterpret_cast<float2*>(&C[(size_t)rm0 * N + cn])       = make_float2(v0, v1);
            *reinterpret_cast<float2*>(&C[(size_t)(rm0 + 8) * N + cn]) = make_float2(v2, v3);
        }
    }
}

// ---------------- fused attention: per (q-tile 64, b*h) block -----------------
// S (64x512) lives in smem; QK^T and PV via TF32 mma; softmax in smem.
// Strides: Ssm 516 (=4 mod 32), Q/K tile 68 (=4 mod 32), V tile 72 (=8 mod 32).
#define SSS   516
#define KST   68
#define VST   72
#define ATTN_SMEM_BYTES ((64*SSS + 64*VST) * 4)

__global__ __launch_bounds__(256) void fused_attn_kernel(const float* __restrict__ qkv) {
    extern __shared__ float smem[];
    float*    Ssm = smem;                                   // 64 x 516
    uint32_t* KV  = reinterpret_cast<uint32_t*>(smem + 64 * SSS); // 64 x 72 (reused Q/K/V)

    int bh = blockIdx.y; int b = bh / NHh, h = bh - b * NHh;
    int qt = blockIdx.x * 64;
    int tid = threadIdx.x, lane = tid & 31, warp = tid >> 5;
    int g = lane >> 2, tig = lane & 3;
    int wq = warp >> 1, wh = warp & 1;     // 4 q sub-tiles x 2 col-halves

    // ---- load Q tile (64x64) into KV as tf32, stride KST ----
#pragma unroll
    for (int i = 0; i < 4; i++) {
        int idx = tid + i * 256;
        int r = idx >> 4, c4 = (idx & 15) << 2;
        float4 v = *reinterpret_cast<const float4*>(
            &qkv[(size_t)(b * Ss + qt + r) * H3 + h * DHh + c4]);
        uint32_t* p = &KV[r * KST + c4];
        p[0] = f2tf32(v.x); p[1] = f2tf32(v.y);
        p[2] = f2tf32(v.z); p[3] = f2tf32(v.w);
    }
    __syncthreads();

    // ---- extract Q A-fragments into registers (rows wq*16..+16, all 64 dh) ----
    uint32_t qa[8][4];
#pragma unroll
    for (int ks = 0; ks < 8; ks++) {
        int rm = wq * 16 + g;
        qa[ks][0] = KV[rm * KST + ks * 8 + tig];
        qa[ks][1] = KV[(rm + 8) * KST + ks * 8 + tig];
        qa[ks][2] = KV[rm * KST + ks * 8 + tig + 4];
        qa[ks][3] = KV[(rm + 8) * KST + ks * 8 + tig + 4];
    }
    __syncthreads();

    // ---- S = Q @ K^T / 8, tile by tile over k-positions ----
    for (int kt = 0; kt < 8; kt++) {
#pragma unroll
        for (int i = 0; i < 4; i++) {
            int idx = tid + i * 256;
            int r = idx >> 4, c4 = (idx & 15) << 2;
            float4 v = *reinterpret_cast<const float4*>(
                &qkv[(size_t)(b * Ss + kt * 64 + r) * H3 + Hh + h * DHh + c4]);
            uint32_t* p = &KV[r * KST + c4];
            p[0] = f2tf32(v.x); p[1] = f2tf32(v.y);
            p[2] = f2tf32(v.z); p[3] = f2tf32(v.w);
        }
        __syncthreads();
        float acc[4][4];
#pragma unroll
        for (int nt = 0; nt < 4; nt++)
#pragma unroll
            for (int r = 0; r < 4; r++) acc[nt][r] = 0.f;
#pragma unroll
        for (int ks = 0; ks < 8; ks++) {
            uint32_t bf[4][2];
#pragma unroll
            for (int nt = 0; nt < 4; nt++) {
                int n = wh * 32 + nt * 8 + g;
                bf[nt][0] = KV[n * KST + ks * 8 + tig];
                bf[nt][1] = KV[n * KST + ks * 8 + tig + 4];
            }
#pragma unroll
            for (int nt = 0; nt < 4; nt++)
                mma_tf32(acc[nt], qa[ks], bf[nt]);
        }
#pragma unroll
        for (int nt = 0; nt < 4; nt++) {
            int col = kt * 64 + wh * 32 + nt * 8 + 2 * tig;
            int row = wq * 16 + g;
            Ssm[row * SSS + col]           = acc[nt][0] * 0.125f;
            Ssm[row * SSS + col + 1]       = acc[nt][1] * 0.125f;
            Ssm[(row + 8) * SSS + col]     = acc[nt][2] * 0.125f;
            Ssm[(row + 8) * SSS + col + 1] = acc[nt][3] * 0.125f;
        }
        __syncthreads();
    }

    // ---- softmax over each row of 512 (one warp per 8 rows) ----
    for (int r = warp * 8; r < warp * 8 + 8; r++) {
        float* row = &Ssm[r * SSS];
        float v[16];
        float m = -1e30f;
#pragma unroll
        for (int i = 0; i < 16; i++) { v[i] = row[lane + 32 * i]; m = fmaxf(m, v[i]); }
#pragma unroll
        for (int o = 16; o > 0; o >>= 1) m = fmaxf(m, __shfl_xor_sync(0xffffffffu, m, o));
        float s = 0.f;
#pragma unroll
        for (int i = 0; i < 16; i++) { v[i] = __expf(v[i] - m); s += v[i]; }
#pragma unroll
        for (int o = 16; o > 0; o >>= 1) s += __shfl_xor_sync(0xffffffffu, s, o);
        float inv = 1.0f / s;
#pragma unroll
        for (int i = 0; i < 16; i++) row[lane + 32 * i] = v[i] * inv;
    }
    __syncthreads();

    // ---- O = P @ V ----
    float oacc[4][4];
#pragma unroll
    for (int nt = 0; nt < 4; nt++)
#pragma unroll
        for (int r = 0; r < 4; r++) oacc[nt][r] = 0.f;

    for (int kt = 0; kt < 8; kt++) {
#pragma unroll
        for (int i = 0; i < 4; i++) {
            int idx = tid + i * 256;
            int r = idx >> 4, c4 = (idx & 15) << 2;
            float4 v = *reinterpret_cast<const float4*>(
                &qkv[(size_t)(b * Ss + kt * 64 + r) * H3 + 2 * Hh + h * DHh + c4]);
            uint32_t* p = &KV[r * VST + c4];
            p[0] = f2tf32(v.x); p[1] = f2tf32(v.y);
            p[2] = f2tf32(v.z); p[3] = f2tf32(v.w);
        }
        __syncthreads();
#pragma unroll
        for (int ks = 0; ks < 8; ks++) {
            uint32_t pa[4];
            int rm = wq * 16 + g;
            int kc = kt * 64 + ks * 8;
            pa[0] = f2tf32(Ssm[rm * SSS + kc + tig]);
            pa[1] = f2tf32(Ssm[(rm + 8) * SSS + kc + tig]);
            pa[2] = f2tf32(Ssm[rm * SSS + kc + tig + 4]);
            pa[3] = f2tf32(Ssm[(rm + 8) * SSS + kc + tig + 4]);
#pragma unroll
            for (int nt = 0; nt < 4; nt++) {
                uint32_t bf[2];
                int n = wh * 32 + nt * 8 + g;
                bf[0] = KV[(ks * 8 + tig) * VST + n];
                bf[1] = KV[(ks * 8 + tig + 4) * VST + n];
                mma_tf32(oacc[nt], pa, bf);
            }
        }
        __syncthreads();
    }

    // ---- store O tile to ctx ----
#pragma unroll
    for (int nt = 0; nt < 4; nt++) {
        int col = h * DHh + wh * 32 + nt * 8 + 2 * tig;
        size_t row = (size_t)(b * Ss + qt + wq * 16 + g);
        *reinterpret_cast<float2*>(&g_ctx[row * Hh + col]) =
            make_float2(oacc[nt][0], oacc[nt][1]);
        *reinterpret_cast<float2*>(&g_ctx[(row + 8) * Hh + col]) =
            make_float2(oacc[nt][2], oacc[nt][3]);
    }
}

// ---------------- segment bookkeeping (deterministic) ----------------
__global__ void seg_prep_kernel(const int* __restrict__ tok) {
    int b = blockIdx.x, s = threadIdx.x;
    __shared__ int sc[Ss];
    __shared__ int cnt[Ss];
    int wid = tok[(b * Ss + s) * 2];
    int isnew = (s == 0) ? 1 : (wid != tok[(b * Ss + s - 1) * 2] ? 1 : 0);
    sc[s] = isnew; cnt[s] = 0; __syncthreads();
    for (int off = 1; off < Ss; off <<= 1) {
        int v = (s >= off) ? sc[s - off] : 0;
        __syncthreads();
        sc[s] += v;
        __syncthreads();
    }
    int gid = sc[s] - 1;
    if (tok[(b * Ss + s) * 2 + 1] != 0) atomicAdd(&cnt[gid], 1);
    if (isnew) g_seg_first[b * Ss + gid] = s;
    __syncthreads();
    g_seg_cnt[b * Ss + s] = cnt[s];
    if (s == Ss - 1) g_nseg[b] = gid + 1;
}

__global__ void seg_mean_kernel(const int* __restrict__ tok, float* __restrict__ out) {
    int g = blockIdx.x, b = blockIdx.y;
    int n = g_nseg[b];
    if (g >= n) return;
    int c = g_seg_cnt[b * Ss + g];
    if (c == 0) return;
    int start = g_seg_first[b * Ss + g];
    int end = (g + 1 < n) ? g_seg_first[b * Ss + g + 1] : Ss;
    __shared__ unsigned char mf[Ss];
    for (int s = threadIdx.x; s < Ss; s += 128)
        mf[s] = (tok[(b * Ss + s) * 2 + 1] != 0);
    __syncthreads();
    float inv = 1.0f / (float)c;
    for (int j = threadIdx.x; j < Hh; j += 128) {
        float sum = 0.f;
        for (int s = start; s < end; s++)
            if (mf[s]) sum += g_x[(size_t)(b * Ss + s) * Hh + j];
        out[(size_t)(b * Ss + g) * Hh + j] = sum * inv;
    }
}

// ---------------- launch ----------------
extern "C" void kernel_launch(void* const* d_in, const int* in_sizes, int n_in,
                              void* d_out, int out_size) {
    const int*   tok  = (const int*)  d_in[0];
    const float* emb  = (const float*)d_in[1];
    const float* pos  = (const float*)d_in[2];
    const float* lng  = (const float*)d_in[3];
    const float* lnb  = (const float*)d_in[4];
    const float* Wqkv = (const float*)d_in[5];
    const float* bqkv = (const float*)d_in[6];
    const float* Wo   = (const float*)d_in[7];
    const float* bo   = (const float*)d_in[8];
    const float* ln1g = (const float*)d_in[9];
    const float* ln1b = (const float*)d_in[10];
    const float* Wff1 = (const float*)d_in[11];
    const float* bff1 = (const float*)d_in[12];
    const float* Wff2 = (const float*)d_in[13];
    const float* bff2 = (const float*)d_in[14];
    const float* ln2g = (const float*)d_in[15];
    const float* ln2b = (const float*)d_in[16];
    float* out = (float*)d_out;

    void* p;
    cudaGetSymbolAddress(&p, g_x);   float* x   = (float*)p;
    cudaGetSymbolAddress(&p, g_tmp); float* tmp = (float*)p;
    cudaGetSymbolAddress(&p, g_ctx); float* ctx = (float*)p;

    static int attn_attr_set = 0;
    if (!attn_attr_set) {
        cudaFuncSetAttribute(fused_attn_kernel,
                             cudaFuncAttributeMaxDynamicSharedMemorySize,
                             ATTN_SMEM_BYTES);
        attn_attr_set = 1;
    }

    cudaMemsetAsync(d_out, 0, (size_t)out_size * sizeof(float), 0);

    embed_ln_kernel<<<Tt, 256>>>(tok, emb, pos, lng, lnb);

    for (int l = 0; l < Ll; l++) {
        // QKV projection: [8192,768] @ [768,2304]
        gemm_tf32_kernel<<<dim3(H3 / 128, Tt / 128), 256>>>(
            x, Wqkv + (size_t)l * Hh * H3, bqkv + l * H3, tmp, Tt, H3, Hh, 0);
        // fused attention (scores + softmax + AV in one kernel)
        fused_attn_kernel<<<dim3(8, Bb * NHh), 256, ATTN_SMEM_BYTES>>>(tmp);
        // output projection: [8192,768] @ [768,768]
        gemm_tf32_kernel<<<dim3(Hh / 128, Tt / 128), 256>>>(
            ctx, Wo + (size_t)l * Hh * Hh, bo + l * Hh, tmp, Tt, Hh, Hh, 0);
        add_ln_kernel<<<Tt, 256>>>(x, tmp, ln1g + l * Hh, ln1b + l * Hh, x);
        // FFN
        gemm_tf32_kernel<<<dim3(FFf / 128, Tt / 128), 256>>>(
            x, Wff1 + (size_t)l * Hh * FFf, bff1 + l * FFf, tmp, Tt, FFf, Hh, 1);
        gemm_tf32_kernel<<<dim3(Hh / 128, Tt / 128), 256>>>(
            tmp, Wff2 + (size_t)l * FFf * Hh, bff2 + l * Hh, ctx, Tt, Hh, FFf, 0);
        add_ln_kernel<<<Tt, 256>>>(x, ctx, ln2g + l * Hh, ln2b + l * Hh, x);
    }

    seg_prep_kernel<<<Bb, Ss>>>(tok);
    seg_mean_kernel<<<dim3(Ss, Bb), 128>>>(tok, out);
}

// round 5
// speedup vs baseline: 3.1420x; 1.0978x over previous
#include <cuda_runtime.h>
#include <math.h>
#include <stdint.h>

#define Bb   16
#define Ss   512
#define Hh   768
#define NHh  12
#define DHh  64
#define Ll   2
#define FFf  3072
#define Tt   (Bb*Ss)          // 8192 tokens
#define H3   (3*Hh)           // 2304

// ---------------- scratch (no allocations allowed) ----------------
__device__ float g_x[Tt*Hh];                    // hidden state      25 MB
__device__ float g_tmp[Tt*FFf];                 // qkv / wo / ff1   100 MB
__device__ float g_ctx[Tt*Hh];                  // attn ctx / ff2    25 MB
__device__ int   g_seg_first[Bb*Ss];
__device__ int   g_seg_cnt[Bb*Ss];
__device__ int   g_nseg[Bb];

// ---------------- helpers ----------------
__device__ __forceinline__ float block_reduce_sum_256(float v, float* red) {
    int t = threadIdx.x;
    red[t] = v; __syncthreads();
#pragma unroll
    for (int o = 128; o > 0; o >>= 1) {
        if (t < o) red[t] += red[t + o];
        __syncthreads();
    }
    float r = red[0];
    __syncthreads();
    return r;
}

__device__ __forceinline__ uint32_t f2tf32(float x) {
    uint32_t r;
    asm("cvt.rna.tf32.f32 %0, %1;" : "=r"(r) : "f"(x));
    return r;
}

__device__ __forceinline__ void mma_tf32(float* c, const uint32_t* a, const uint32_t* b) {
    asm volatile(
        "mma.sync.aligned.m16n8k8.row.col.f32.tf32.tf32.f32 "
        "{%0,%1,%2,%3}, {%4,%5,%6,%7}, {%8,%9}, {%0,%1,%2,%3};"
        : "+f"(c[0]), "+f"(c[1]), "+f"(c[2]), "+f"(c[3])
        : "r"(a[0]), "r"(a[1]), "r"(a[2]), "r"(a[3]), "r"(b[0]), "r"(b[1]));
}

__device__ __forceinline__ void cp_async16(void* smem_ptr, const void* gptr) {
    uint32_t s = (uint32_t)__cvta_generic_to_shared(smem_ptr);
    asm volatile("cp.async.cg.shared.global [%0], [%1], 16;" :: "r"(s), "l"(gptr));
}

// raw fp32 bits + half tf32 ulp; HW mma truncates low 13 bits => effective RNA
#define RND_TF32(x) ((x) + 0x1000u)

// ---------------- embedding + LN ----------------
__global__ void embed_ln_kernel(const int* __restrict__ tok,
                                const float* __restrict__ emb,
                                const float* __restrict__ pos,
                                const float* __restrict__ g,
                                const float* __restrict__ bt) {
    int row = blockIdx.x;
    int s   = row & (Ss - 1);
    int id  = tok[row * 2 + 1];
    __shared__ float y[Hh];
    __shared__ float red[256];
    int t = threadIdx.x;
    float part = 0.f;
    for (int j = t; j < Hh; j += 256) {
        float v = emb[(size_t)id * Hh + j] + pos[s * Hh + j];
        y[j] = v; part += v;
    }
    float mean = block_reduce_sum_256(part, red) * (1.f / Hh);
    part = 0.f;
    for (int j = t; j < Hh; j += 256) { float d = y[j] - mean; part += d * d; }
    float var = block_reduce_sum_256(part, red) * (1.f / Hh);
    float inv = rsqrtf(var + 1e-12f);
    for (int j = t; j < Hh; j += 256)
        g_x[(size_t)row * Hh + j] = (y[j] - mean) * inv * g[j] + bt[j];
}

// ---------------- residual add + LN ----------------
__global__ void add_ln_kernel(const float* __restrict__ x,
                              const float* __restrict__ tadd,
                              const float* __restrict__ g,
                              const float* __restrict__ bt,
                              float* __restrict__ out) {
    int row = blockIdx.x;
    size_t base = (size_t)row * Hh;
    __shared__ float y[Hh];
    __shared__ float red[256];
    int t = threadIdx.x;
    float part = 0.f;
    for (int j = t; j < Hh; j += 256) {
        float v = x[base + j] + tadd[base + j];
        y[j] = v; part += v;
    }
    float mean = block_reduce_sum_256(part, red) * (1.f / Hh);
    part = 0.f;
    for (int j = t; j < Hh; j += 256) { float d = y[j] - mean; part += d * d; }
    float var = block_reduce_sum_256(part, red) * (1.f / Hh);
    float inv = rsqrtf(var + 1e-12f);
    for (int j = t; j < Hh; j += 256)
        out[base + j] = (y[j] - mean) * inv * g[j] + bt[j];
}

// ---------------- TF32 tensor-core GEMM with 3-stage cp.async pipeline ---------
// C = A[M,K] @ W[K,N] + bias, optional GELU. BM=BN=128, BK=32, 8 warps (2x4).
#define AS_STRIDE 36
#define BS_STRIDE 132
#define AS_SZ     (128 * AS_STRIDE)          // 4608 u32
#define BS_SZ     (32 * BS_STRIDE)           // 4224 u32
#define STAGE_SZ  (AS_SZ + BS_SZ)            // 8832 u32
#define NSTAGE    3
#define GEMM_SMEM_BYTES (NSTAGE * STAGE_SZ * 4)   // 105984 B

__device__ __forceinline__ void gemm_load_stage(uint32_t* stage,
                                                const float* A, const float* W,
                                                int N, int K,
                                                int mBase, int nBase, int k0, int tid) {
#pragma unroll
    for (int i = 0; i < 4; i++) {
        int idx = tid + i * 256;
        int r = idx >> 3, c4 = (idx & 7) << 2;
        cp_async16(&stage[r * AS_STRIDE + c4],
                   &A[(size_t)(mBase + r) * K + k0 + c4]);
    }
    uint32_t* bs = stage + AS_SZ;
#pragma unroll
    for (int i = 0; i < 4; i++) {
        int idx = tid + i * 256;
        int r = idx >> 5, c4 = (idx & 31) << 2;
        cp_async16(&bs[r * BS_STRIDE + c4],
                   &W[(size_t)(k0 + r) * N + nBase + c4]);
    }
    asm volatile("cp.async.commit_group;" ::: "memory");
}

__global__ __launch_bounds__(256) void gemm_tf32_kernel(const float* __restrict__ A,
                                                        const float* __restrict__ W,
                                                        const float* __restrict__ bias,
                                                        float* __restrict__ C,
                                                        int M, int N, int K, int act) {
    extern __shared__ uint32_t sm[];
    int tid  = threadIdx.x;
    int lane = tid & 31;
    int warp = tid >> 5;
    int g    = lane >> 2, tig = lane & 3;
    int wm   = warp >> 2, wn = warp & 3;
    int mBase = blockIdx.y * 128, nBase = blockIdx.x * 128;

    float acc[4][4][4];
#pragma unroll
    for (int i = 0; i < 4; i++)
#pragma unroll
        for (int j = 0; j < 4; j++)
#pragma unroll
            for (int r = 0; r < 4; r++) acc[i][j][r] = 0.f;

    int nK = K >> 5;
    gemm_load_stage(sm,            A, W, N, K, mBase, nBase, 0,  tid);
    gemm_load_stage(sm + STAGE_SZ, A, W, N, K, mBase, nBase, 32, tid);

    int s_cur = 0, s_next = 2;
    for (int i = 0; i < nK; i++) {
        if (i + 2 < nK) {
            gemm_load_stage(sm + s_next * STAGE_SZ, A, W, N, K,
                            mBase, nBase, (i + 2) << 5, tid);
            asm volatile("cp.async.wait_group 2;" ::: "memory");
        } else if (i + 1 < nK) {
            asm volatile("cp.async.wait_group 1;" ::: "memory");
        } else {
            asm volatile("cp.async.wait_group 0;" ::: "memory");
        }
        __syncthreads();

        const uint32_t* As = sm + s_cur * STAGE_SZ;
        const uint32_t* Bs = As + AS_SZ;
#pragma unroll
        for (int kk = 0; kk < 32; kk += 8) {
            uint32_t a[4][4], b[4][2];
#pragma unroll
            for (int mi = 0; mi < 4; mi++) {
                int rm = wm * 64 + mi * 16 + g;
                a[mi][0] = RND_TF32(As[rm * AS_STRIDE + kk + tig]);
                a[mi][1] = RND_TF32(As[(rm + 8) * AS_STRIDE + kk + tig]);
                a[mi][2] = RND_TF32(As[rm * AS_STRIDE + kk + tig + 4]);
                a[mi][3] = RND_TF32(As[(rm + 8) * AS_STRIDE + kk + tig + 4]);
            }
#pragma unroll
            for (int ni = 0; ni < 4; ni++) {
                int cn = wn * 32 + ni * 8 + g;
                b[ni][0] = RND_TF32(Bs[(kk + tig) * BS_STRIDE + cn]);
                b[ni][1] = RND_TF32(Bs[(kk + tig + 4) * BS_STRIDE + cn]);
            }
#pragma unroll
            for (int mi = 0; mi < 4; mi++)
#pragma unroll
                for (int ni = 0; ni < 4; ni++)
                    mma_tf32(acc[mi][ni], a[mi], b[ni]);
        }
        __syncthreads();
        s_cur = (s_cur == 2) ? 0 : s_cur + 1;
        s_next = (s_next == 2) ? 0 : s_next + 1;
    }

    // epilogue: bias + optional exact GELU, float2 stores
#pragma unroll
    for (int mi = 0; mi < 4; mi++) {
        int rm0 = mBase + wm * 64 + mi * 16 + g;
#pragma unroll
        for (int ni = 0; ni < 4; ni++) {
            int cn = nBase + wn * 32 + ni * 8 + 2 * tig;
            float b0 = bias[cn], b1 = bias[cn + 1];
            float v0 = acc[mi][ni][0] + b0;
            float v1 = acc[mi][ni][1] + b1;
            float v2 = acc[mi][ni][2] + b0;
            float v3 = acc[mi][ni][3] + b1;
            if (act) {
                v0 = 0.5f * v0 * (1.0f + erff(v0 * 0.70710678118654752f));
                v1 = 0.5f * v1 * (1.0f + erff(v1 * 0.70710678118654752f));
                v2 = 0.5f * v2 * (1.0f + erff(v2 * 0.70710678118654752f));
                v3 = 0.5f * v3 * (1.0f + erff(v3 * 0.70710678118654752f));
            }
            *reinterpret_cast<float2*>(&C[(size_t)rm0 * N + cn])       = make_float2(v0, v1);
            *reinterpret_cast<float2*>(&C[(size_t)(rm0 + 8) * N + cn]) = make_float2(v2, v3);
        }
    }
}

// ---------------- fused attention: per (q-tile 64, b*h) block -----------------
#define SSS   516
#define KST   68
#define VST   72
#define ATTN_SMEM_BYTES ((64*SSS + 64*VST) * 4)

__global__ __launch_bounds__(256) void fused_attn_kernel(const float* __restrict__ qkv) {
    extern __shared__ float smem[];
    float*    Ssm = smem;                                        // 64 x 516
    uint32_t* KV  = reinterpret_cast<uint32_t*>(smem + 64 * SSS);// 64 x 72

    int bh = blockIdx.y; int b = bh / NHh, h = bh - b * NHh;
    int qt = blockIdx.x * 64;
    int tid = threadIdx.x, lane = tid & 31, warp = tid >> 5;
    int g = lane >> 2, tig = lane & 3;
    int wq = warp >> 1, wh = warp & 1;

#pragma unroll
    for (int i = 0; i < 4; i++) {
        int idx = tid + i * 256;
        int r = idx >> 4, c4 = (idx & 15) << 2;
        float4 v = *reinterpret_cast<const float4*>(
            &qkv[(size_t)(b * Ss + qt + r) * H3 + h * DHh + c4]);
        uint32_t* p = &KV[r * KST + c4];
        p[0] = f2tf32(v.x); p[1] = f2tf32(v.y);
        p[2] = f2tf32(v.z); p[3] = f2tf32(v.w);
    }
    __syncthreads();

    uint32_t qa[8][4];
#pragma unroll
    for (int ks = 0; ks < 8; ks++) {
        int rm = wq * 16 + g;
        qa[ks][0] = KV[rm * KST + ks * 8 + tig];
        qa[ks][1] = KV[(rm + 8) * KST + ks * 8 + tig];
        qa[ks][2] = KV[rm * KST + ks * 8 + tig + 4];
        qa[ks][3] = KV[(rm + 8) * KST + ks * 8 + tig + 4];
    }
    __syncthreads();

    for (int kt = 0; kt < 8; kt++) {
#pragma unroll
        for (int i = 0; i < 4; i++) {
            int idx = tid + i * 256;
            int r = idx >> 4, c4 = (idx & 15) << 2;
            float4 v = *reinterpret_cast<const float4*>(
                &qkv[(size_t)(b * Ss + kt * 64 + r) * H3 + Hh + h * DHh + c4]);
            uint32_t* p = &KV[r * KST + c4];
            p[0] = f2tf32(v.x); p[1] = f2tf32(v.y);
            p[2] = f2tf32(v.z); p[3] = f2tf32(v.w);
        }
        __syncthreads();
        float acc[4][4];
#pragma unroll
        for (int nt = 0; nt < 4; nt++)
#pragma unroll
            for (int r = 0; r < 4; r++) acc[nt][r] = 0.f;
#pragma unroll
        for (int ks = 0; ks < 8; ks++) {
            uint32_t bf[4][2];
#pragma unroll
            for (int nt = 0; nt < 4; nt++) {
                int n = wh * 32 + nt * 8 + g;
                bf[nt][0] = KV[n * KST + ks * 8 + tig];
                bf[nt][1] = KV[n * KST + ks * 8 + tig + 4];
            }
#pragma unroll
            for (int nt = 0; nt < 4; nt++)
                mma_tf32(acc[nt], qa[ks], bf[nt]);
        }
#pragma unroll
        for (int nt = 0; nt < 4; nt++) {
            int col = kt * 64 + wh * 32 + nt * 8 + 2 * tig;
            int row = wq * 16 + g;
            Ssm[row * SSS + col]           = acc[nt][0] * 0.125f;
            Ssm[row * SSS + col + 1]       = acc[nt][1] * 0.125f;
            Ssm[(row + 8) * SSS + col]     = acc[nt][2] * 0.125f;
            Ssm[(row + 8) * SSS + col + 1] = acc[nt][3] * 0.125f;
        }
        __syncthreads();
    }

    for (int r = warp * 8; r < warp * 8 + 8; r++) {
        float* row = &Ssm[r * SSS];
        float v[16];
        float m = -1e30f;
#pragma unroll
        for (int i = 0; i < 16; i++) { v[i] = row[lane + 32 * i]; m = fmaxf(m, v[i]); }
#pragma unroll
        for (int o = 16; o > 0; o >>= 1) m = fmaxf(m, __shfl_xor_sync(0xffffffffu, m, o));
        float s = 0.f;
#pragma unroll
        for (int i = 0; i < 16; i++) { v[i] = __expf(v[i] - m); s += v[i]; }
#pragma unroll
        for (int o = 16; o > 0; o >>= 1) s += __shfl_xor_sync(0xffffffffu, s, o);
        float inv = 1.0f / s;
#pragma unroll
        for (int i = 0; i < 16; i++) row[lane + 32 * i] = v[i] * inv;
    }
    __syncthreads();

    float oacc[4][4];
#pragma unroll
    for (int nt = 0; nt < 4; nt++)
#pragma unroll
        for (int r = 0; r < 4; r++) oacc[nt][r] = 0.f;

    for (int kt = 0; kt < 8; kt++) {
#pragma unroll
        for (int i = 0; i < 4; i++) {
            int idx = tid + i * 256;
            int r = idx >> 4, c4 = (idx & 15) << 2;
            float4 v = *reinterpret_cast<const float4*>(
                &qkv[(size_t)(b * Ss + kt * 64 + r) * H3 + 2 * Hh + h * DHh + c4]);
            uint32_t* p = &KV[r * VST + c4];
            p[0] = f2tf32(v.x); p[1] = f2tf32(v.y);
            p[2] = f2tf32(v.z); p[3] = f2tf32(v.w);
        }
        __syncthreads();
#pragma unroll
        for (int ks = 0; ks < 8; ks++) {
            uint32_t pa[4];
            int rm = wq * 16 + g;
            int kc = kt * 64 + ks * 8;
            pa[0] = f2tf32(Ssm[rm * SSS + kc + tig]);
            pa[1] = f2tf32(Ssm[(rm + 8) * SSS + kc + tig]);
            pa[2] = f2tf32(Ssm[rm * SSS + kc + tig + 4]);
            pa[3] = f2tf32(Ssm[(rm + 8) * SSS + kc + tig + 4]);
#pragma unroll
            for (int nt = 0; nt < 4; nt++) {
                uint32_t bf[2];
                int n = wh * 32 + nt * 8 + g;
                bf[0] = KV[(ks * 8 + tig) * VST + n];
                bf[1] = KV[(ks * 8 + tig + 4) * VST + n];
                mma_tf32(oacc[nt], pa, bf);
            }
        }
        __syncthreads();
    }

#pragma unroll
    for (int nt = 0; nt < 4; nt++) {
        int col = h * DHh + wh * 32 + nt * 8 + 2 * tig;
        size_t row = (size_t)(b * Ss + qt + wq * 16 + g);
        *reinterpret_cast<float2*>(&g_ctx[row * Hh + col]) =
            make_float2(oacc[nt][0], oacc[nt][1]);
        *reinterpret_cast<float2*>(&g_ctx[(row + 8) * Hh + col]) =
            make_float2(oacc[nt][2], oacc[nt][3]);
    }
}

// ---------------- segment bookkeeping (deterministic) ----------------
__global__ void seg_prep_kernel(const int* __restrict__ tok) {
    int b = blockIdx.x, s = threadIdx.x;
    __shared__ int sc[Ss];
    __shared__ int cnt[Ss];
    int wid = tok[(b * Ss + s) * 2];
    int isnew = (s == 0) ? 1 : (wid != tok[(b * Ss + s - 1) * 2] ? 1 : 0);
    sc[s] = isnew; cnt[s] = 0; __syncthreads();
    for (int off = 1; off < Ss; off <<= 1) {
        int v = (s >= off) ? sc[s - off] : 0;
        __syncthreads();
        sc[s] += v;
        __syncthreads();
    }
    int gid = sc[s] - 1;
    if (tok[(b * Ss + s) * 2 + 1] != 0) atomicAdd(&cnt[gid], 1);
    if (isnew) g_seg_first[b * Ss + gid] = s;
    __syncthreads();
    g_seg_cnt[b * Ss + s] = cnt[s];
    if (s == Ss - 1) g_nseg[b] = gid + 1;
}

__global__ void seg_mean_kernel(const int* __restrict__ tok, float* __restrict__ out) {
    int g = blockIdx.x, b = blockIdx.y;
    int n = g_nseg[b];
    if (g >= n) return;
    int c = g_seg_cnt[b * Ss + g];
    if (c == 0) return;
    int start = g_seg_first[b * Ss + g];
    int end = (g + 1 < n) ? g_seg_first[b * Ss + g + 1] : Ss;
    __shared__ unsigned char mf[Ss];
    for (int s = threadIdx.x; s < Ss; s += 128)
        mf[s] = (tok[(b * Ss + s) * 2 + 1] != 0);
    __syncthreads();
    float inv = 1.0f / (float)c;
    for (int j = threadIdx.x; j < Hh; j += 128) {
        float sum = 0.f;
        for (int s = start; s < end; s++)
            if (mf[s]) sum += g_x[(size_t)(b * Ss + s) * Hh + j];
        out[(size_t)(b * Ss + g) * Hh + j] = sum * inv;
    }
}

// ---------------- launch ----------------
extern "C" void kernel_launch(void* const* d_in, const int* in_sizes, int n_in,
                              void* d_out, int out_size) {
    const int*   tok  = (const int*)  d_in[0];
    const float* emb  = (const float*)d_in[1];
    const float* pos  = (const float*)d_in[2];
    const float* lng  = (const float*)d_in[3];
    const float* lnb  = (const float*)d_in[4];
    const float* Wqkv = (const float*)d_in[5];
    const float* bqkv = (const float*)d_in[6];
    const float* Wo   = (const float*)d_in[7];
    const float* bo   = (const float*)d_in[8];
    const float* ln1g = (const float*)d_in[9];
    const float* ln1b = (const float*)d_in[10];
    const float* Wff1 = (const float*)d_in[11];
    const float* bff1 = (const float*)d_in[12];
    const float* Wff2 = (const float*)d_in[13];
    const float* bff2 = (const float*)d_in[14];
    const float* ln2g = (const float*)d_in[15];
    const float* ln2b = (const float*)d_in[16];
    float* out = (float*)d_out;

    void* p;
    cudaGetSymbolAddress(&p, g_x);   float* x   = (float*)p;
    cudaGetSymbolAddress(&p, g_tmp); float* tmp = (float*)p;
    cudaGetSymbolAddress(&p, g_ctx); float* ctx = (float*)p;

    cudaFuncSetAttribute(fused_attn_kernel,
                         cudaFuncAttributeMaxDynamicSharedMemorySize,
                         ATTN_SMEM_BYTES);
    cudaFuncSetAttribute(gemm_tf32_kernel,
                         cudaFuncAttributeMaxDynamicSharedMemorySize,
                         GEMM_SMEM_BYTES);

    cudaMemsetAsync(d_out, 0, (size_t)out_size * sizeof(float), 0);

    embed_ln_kernel<<<Tt, 256>>>(tok, emb, pos, lng, lnb);

    for (int l = 0; l < Ll; l++) {
        gemm_tf32_kernel<<<dim3(H3 / 128, Tt / 128), 256, GEMM_SMEM_BYTES>>>(
            x, Wqkv + (size_t)l * Hh * H3, bqkv + l * H3, tmp, Tt, H3, Hh, 0);
        fused_attn_kernel<<<dim3(8, Bb * NHh), 256, ATTN_SMEM_BYTES>>>(tmp);
        gemm_tf32_kernel<<<dim3(Hh / 128, Tt / 128), 256, GEMM_SMEM_BYTES>>>(
            ctx, Wo + (size_t)l * Hh * Hh, bo + l * Hh, tmp, Tt, Hh, Hh, 0);
        add_ln_kernel<<<Tt, 256>>>(x, tmp, ln1g + l * Hh, ln1b + l * Hh, x);
        gemm_tf32_kernel<<<dim3(FFf / 128, Tt / 128), 256, GEMM_SMEM_BYTES>>>(
            x, Wff1 + (size_t)l * Hh * FFf, bff1 + l * FFf, tmp, Tt, FFf, Hh, 1);
        gemm_tf32_kernel<<<dim3(Hh / 128, Tt / 128), 256, GEMM_SMEM_BYTES>>>(
            tmp, Wff2 + (size_t)l * FFf * Hh, bff2 + l * Hh, ctx, Tt, Hh, FFf, 0);
        add_ln_kernel<<<Tt, 256>>>(x, ctx, ln2g + l * Hh, ln2b + l * Hh, x);
    }

    seg_prep_kernel<<<Bb, Ss>>>(tok);
    seg_mean_kernel<<<dim3(Ss, Bb), 128>>>(tok, out);
}